// round 1
// baseline (speedup 1.0000x reference)
#include <cuda_runtime.h>
#include <cstdint>

// Fixed problem shape (SoftAggBasic): x [B,N,D] f32, ix [N], S segments.
constexpr int B = 8;
constexpr int N = 65536;
constexpr int D = 512;
constexpr int S = 1024;

// ---------------- device scratch (no allocations allowed) ----------------
__device__ int   g_ix[N];
__device__ int   g_counts[S];
__device__ int   g_offs[S + 1];
__device__ int   g_cursor[S];
__device__ int   g_perm[N];
__device__ float g_xbar[(size_t)B * S * D];  // 16 MB
__device__ float g_Wc[(size_t)D * D];        // Wf @ Wh
__device__ float g_bc[D];                    // bf @ Wh + bh
__device__ float g_z[(size_t)B * S * D];     // 16 MB

// ---------------- ix normalization (int64 vs int32 autodetect) ----------------
__global__ void k_fix_ix(const int* __restrict__ raw) {
    int n = blockIdx.x * blockDim.x + threadIdx.x;
    // If the tensor is int64 little-endian with values in [0,1024), every odd
    // 32-bit word of the first 16 elements is 0. For int32 random data in
    // [0,1024) the probability of that is (1/1024)^16 ~ 0.
    int any = 0;
#pragma unroll
    for (int i = 0; i < 16; i++) any |= raw[2 * i + 1];
    int v = (any == 0) ? raw[2 * n] : raw[n];
    g_ix[n] = v;
}

// ---------------- counting sort of rows by segment ----------------
__global__ void k_zero() {
    int i = blockIdx.x * blockDim.x + threadIdx.x;
    if (i < S) g_counts[i] = 0;
}

__global__ void k_count() {
    int n = blockIdx.x * blockDim.x + threadIdx.x;
    atomicAdd(&g_counts[g_ix[n]], 1);
}

__global__ void k_scan() {  // single block, S=1024 threads
    __shared__ int sh[S];
    int t = threadIdx.x;
    int c = g_counts[t];
    sh[t] = c;
    __syncthreads();
#pragma unroll
    for (int off = 1; off < S; off <<= 1) {
        int v = (t >= off) ? sh[t - off] : 0;
        __syncthreads();
        sh[t] += v;
        __syncthreads();
    }
    g_offs[t + 1] = sh[t];
    if (t == 0) g_offs[0] = 0;
    g_cursor[t] = sh[t] - c;  // exclusive prefix = segment start
}

__global__ void k_scatter() {
    int n = blockIdx.x * blockDim.x + threadIdx.x;
    int s = g_ix[n];
    int p = atomicAdd(&g_cursor[s], 1);
    g_perm[p] = n;
}

// ---------------- pass 1: fused logits + softmax + weighted segment mean ---
// One CTA per (segment, batch). Each of 256 threads owns 2 feature dims
// (float2). Per row: load x-row (2 KB) into registers, block-reduce dot with
// Wg -> logit, e = exp(logit), accumulate e*x and sum(e). x is read from HBM
// exactly once for the whole problem. Softmax max-shift is skipped: logits
// ~ N(0,1), identical result mathematically.
__global__ __launch_bounds__(256) void k_pass1(const float* __restrict__ x,
                                               const float* __restrict__ Wg,
                                               const float* __restrict__ bg) {
    int s = blockIdx.x, b = blockIdx.y;
    int t = threadIdx.x;
    int lane = t & 31, wid = t >> 5;
    float2 wg = ((const float2*)Wg)[t];
    float bg0 = bg[0];
    int start = g_offs[s], end = g_offs[s + 1];

    float ax = 0.f, ay = 0.f, denom = 0.f;
    __shared__ float red[8][4];
    const float2* x2 = (const float2*)x;

    for (int r = start; r < end; r += 4) {
        float2 xv[4];
        float p[4];
#pragma unroll
        for (int i = 0; i < 4; i++) {
            int rr = r + i;
            int nrow = g_perm[(rr < end) ? rr : start];  // clamp: e masked below
            xv[i] = x2[((size_t)b * N + nrow) * (D / 2) + t];
            p[i] = xv[i].x * wg.x + xv[i].y * wg.y;
        }
        // warp reduce 4 rows at once
#pragma unroll
        for (int off = 16; off; off >>= 1) {
#pragma unroll
            for (int i = 0; i < 4; i++) p[i] += __shfl_xor_sync(0xffffffffu, p[i], off);
        }
        if (lane < 4) red[wid][lane] = p[lane];
        __syncthreads();
        float lsum[4] = {0.f, 0.f, 0.f, 0.f};
#pragma unroll
        for (int w = 0; w < 8; w++) {
            lsum[0] += red[w][0];
            lsum[1] += red[w][1];
            lsum[2] += red[w][2];
            lsum[3] += red[w][3];
        }
        __syncthreads();
#pragma unroll
        for (int i = 0; i < 4; i++) {
            float e = (r + i < end) ? expf(lsum[i] + bg0) : 0.f;
            ax += e * xv[i].x;
            ay += e * xv[i].y;
            denom += e;
        }
    }
    float inv = (denom > 0.f) ? 1.f / denom : 0.f;
    float2 o;
    o.x = ax * inv;
    o.y = ay * inv;
    ((float2*)g_xbar)[((size_t)b * S + s) * (D / 2) + t] = o;
}

// ---------------- fold weights: Wc = Wf @ Wh, bc = bf @ Wh + bh ----------------
__global__ void k_bc(const float* __restrict__ Wh, const float* __restrict__ bf,
                     const float* __restrict__ bh) {
    int d = blockIdx.x * blockDim.x + threadIdx.x;
    float acc = bh[d];
    for (int k = 0; k < D; k++) acc += bf[k] * Wh[(size_t)k * D + d];
    g_bc[d] = acc;
}

__global__ __launch_bounds__(256) void k_wc(const float* __restrict__ Wf,
                                            const float* __restrict__ Wh) {
    __shared__ float Af[32][33], Bf[32][33];
    int t = threadIdx.x;
    int row0 = blockIdx.y * 32, col0 = blockIdx.x * 32;
    int c = t & 31, g = t >> 5;  // g in 0..7, 4 output rows each
    float acc[4] = {0.f, 0.f, 0.f, 0.f};
    for (int k0 = 0; k0 < D; k0 += 32) {
#pragma unroll
        for (int i = 0; i < 4; i++) {
            int idx = t + i * 256;
            int r = idx >> 5, cc = idx & 31;
            Af[r][cc] = Wf[(size_t)(row0 + r) * D + k0 + cc];
            Bf[r][cc] = Wh[(size_t)(k0 + r) * D + col0 + cc];
        }
        __syncthreads();
#pragma unroll
        for (int k = 0; k < 32; k++) {
            float bv = Bf[k][c];
#pragma unroll
            for (int i = 0; i < 4; i++) acc[i] += Af[g * 4 + i][k] * bv;
        }
        __syncthreads();
    }
#pragma unroll
    for (int i = 0; i < 4; i++)
        g_Wc[(size_t)(row0 + g * 4 + i) * D + col0 + c] = acc[i];
}

// ---------------- z = xbar @ Wc + bc  (M=B*S=8192, N=K=512) ----------------
// Classic 128x128x8 SIMT SGEMM, 256 threads, 8x8 accumulators per thread.
__global__ __launch_bounds__(256) void k_sgemm() {
    __shared__ float As[8][128];
    __shared__ float Bs[8][128];
    int bx = blockIdx.x, by = blockIdx.y;
    int t = threadIdx.x;
    int tx = t & 15, ty = t >> 4;
    const float* A = g_xbar + (size_t)by * 128 * D;
    const float* Bm = g_Wc + bx * 128;

    float acc[8][8];
#pragma unroll
    for (int i = 0; i < 8; i++)
#pragma unroll
        for (int j = 0; j < 8; j++) acc[i][j] = 0.f;

    int arow = t >> 1, acol = (t & 1) * 4;     // A tile 128x8
    int brow = t >> 5, bcol = (t & 31) * 4;    // B tile 8x128

    for (int k0 = 0; k0 < D; k0 += 8) {
        float4 av = *(const float4*)(A + (size_t)arow * D + k0 + acol);
        float4 bv = *(const float4*)(Bm + (size_t)(k0 + brow) * D + bcol);
        __syncthreads();
        As[acol + 0][arow] = av.x;
        As[acol + 1][arow] = av.y;
        As[acol + 2][arow] = av.z;
        As[acol + 3][arow] = av.w;
        *(float4*)&Bs[brow][bcol] = bv;
        __syncthreads();
#pragma unroll
        for (int k = 0; k < 8; k++) {
            float4 a0 = *(const float4*)&As[k][ty * 4];
            float4 a1 = *(const float4*)&As[k][ty * 4 + 64];
            float4 b0 = *(const float4*)&Bs[k][tx * 4];
            float4 b1 = *(const float4*)&Bs[k][tx * 4 + 64];
            float ar[8] = {a0.x, a0.y, a0.z, a0.w, a1.x, a1.y, a1.z, a1.w};
            float br[8] = {b0.x, b0.y, b0.z, b0.w, b1.x, b1.y, b1.z, b1.w};
#pragma unroll
            for (int i = 0; i < 8; i++)
#pragma unroll
                for (int j = 0; j < 8; j++) acc[i][j] += ar[i] * br[j];
        }
    }

    float bb[8];
#pragma unroll
    for (int j = 0; j < 8; j++) {
        int nn = bx * 128 + ((j < 4) ? tx * 4 + j : 64 + tx * 4 + j - 4);
        bb[j] = g_bc[nn];
    }
#pragma unroll
    for (int i = 0; i < 8; i++) {
        int m = by * 128 + ((i < 4) ? ty * 4 + i : 64 + ty * 4 + i - 4);
        float* crow = g_z + (size_t)m * D + bx * 128;
        float4 o;
        o.x = acc[i][0] + bb[0];
        o.y = acc[i][1] + bb[1];
        o.z = acc[i][2] + bb[2];
        o.w = acc[i][3] + bb[3];
        *(float4*)(crow + tx * 4) = o;
        o.x = acc[i][4] + bb[4];
        o.y = acc[i][5] + bb[5];
        o.z = acc[i][6] + bb[6];
        o.w = acc[i][7] + bb[7];
        *(float4*)(crow + 64 + tx * 4) = o;
    }
}

// ---------------- gather/expand: out[b,n,:] = z[b, ix[n], :] ----------------
// z (16 MB) stays L2-resident; this is a pure 1 GB HBM write stream.
__global__ void k_gather(float* __restrict__ out) {
    size_t id = (size_t)blockIdx.x * 256 + threadIdx.x;  // one float4 per thread
    int d4 = (int)(id & 127);                            // D/4 = 128
    size_t row = id >> 7;                                // b*N + n
    int n = (int)(row & (size_t)(N - 1));
    int b = (int)(row >> 16);                            // N = 65536
    int s = g_ix[n];
    const float4* z4 = (const float4*)g_z;
    ((float4*)out)[id] = z4[((size_t)(b * S + s)) * (D / 4) + d4];
}

// ---------------- launch ----------------
extern "C" void kernel_launch(void* const* d_in, const int* in_sizes, int n_in,
                              void* d_out, int out_size) {
    const float* x  = (const float*)d_in[0];
    const int*   ix = (const int*)d_in[1];
    const float* Wf = (const float*)d_in[2];
    const float* bf = (const float*)d_in[3];
    const float* Wg = (const float*)d_in[4];
    const float* bg = (const float*)d_in[5];
    const float* Wh = (const float*)d_in[6];
    const float* bh = (const float*)d_in[7];
    float* out = (float*)d_out;
    (void)in_sizes; (void)n_in; (void)out_size;

    k_fix_ix<<<N / 256, 256>>>(ix);
    k_zero<<<S / 256, 256>>>();
    k_count<<<N / 256, 256>>>();
    k_scan<<<1, S>>>();
    k_scatter<<<N / 256, 256>>>();

    dim3 g1(S, B);
    k_pass1<<<g1, 256>>>(x, Wg, bg);

    k_bc<<<D / 256, 256>>>(Wh, bf, bh);
    k_wc<<<dim3(D / 32, D / 32), 256>>>(Wf, Wh);

    dim3 g4(D / 128, (B * S) / 128);
    k_sgemm<<<g4, 256>>>();

    size_t total4 = (size_t)B * N * (D / 4);
    k_gather<<<(unsigned)(total4 / 256), 256>>>(out);
}

// round 2
// speedup vs baseline: 1.3984x; 1.3984x over previous
#include <cuda_runtime.h>
#include <cstdint>

// Fixed problem shape (SoftAggBasic): x [B,N,D] f32, ix [N], S segments.
constexpr int B = 8;
constexpr int N = 65536;
constexpr int D = 512;
constexpr int S = 1024;

// ---------------- device scratch (no allocations allowed) ----------------
__device__ int   g_ix[N];
__device__ int   g_counts[S];
__device__ int   g_offs[S + 1];
__device__ int   g_cursor[S];
__device__ int   g_perm[N];
__device__ float g_xbar[(size_t)B * S * D];  // 16 MB
__device__ float g_Wc[(size_t)D * D];        // Wf @ Wh
__device__ float g_bc[D];                    // bf @ Wh + bh
__device__ float g_z[(size_t)B * S * D];     // 16 MB

// ---------------- packed f32x2 helpers (Blackwell FFMA2) ----------------
__device__ __forceinline__ unsigned long long pk2(float x, float y) {
    unsigned long long r;
    asm("mov.b64 %0, {%1,%2};" : "=l"(r) : "f"(x), "f"(y));
    return r;
}
__device__ __forceinline__ float2 upk2(unsigned long long v) {
    float2 r;
    asm("mov.b64 {%0,%1}, %2;" : "=f"(r.x), "=f"(r.y) : "l"(v));
    return r;
}
__device__ __forceinline__ void fma2(unsigned long long& d, unsigned long long a,
                                     unsigned long long b) {
    asm("fma.rn.f32x2 %0, %1, %2, %0;" : "+l"(d) : "l"(a), "l"(b));
}

// ---------------- ix normalization (int64 vs int32 autodetect) + zero counts
__global__ void k_fix_ix(const int* __restrict__ raw) {
    int n = blockIdx.x * blockDim.x + threadIdx.x;
    int any = 0;
#pragma unroll
    for (int i = 0; i < 16; i++) any |= raw[2 * i + 1];
    int v = (any == 0) ? raw[2 * n] : raw[n];
    g_ix[n] = v;
    if (n < S) g_counts[n] = 0;
}

__global__ void k_count() {
    int n = blockIdx.x * blockDim.x + threadIdx.x;
    atomicAdd(&g_counts[g_ix[n]], 1);
}

// single block, S=1024 threads, warp-shfl hierarchical scan
__global__ void k_scan() {
    __shared__ int ws[32];
    int t = threadIdx.x, lane = t & 31, w = t >> 5;
    int c = g_counts[t];
    int v = c;
#pragma unroll
    for (int off = 1; off < 32; off <<= 1) {
        int u = __shfl_up_sync(~0u, v, off);
        if (lane >= off) v += u;
    }
    if (lane == 31) ws[w] = v;
    __syncthreads();
    if (w == 0) {
        int s2 = ws[lane];
#pragma unroll
        for (int off = 1; off < 32; off <<= 1) {
            int u = __shfl_up_sync(~0u, s2, off);
            if (lane >= off) s2 += u;
        }
        ws[lane] = s2;
    }
    __syncthreads();
    int incl = v + (w ? ws[w - 1] : 0);
    g_offs[t + 1] = incl;
    if (t == 0) g_offs[0] = 0;
    g_cursor[t] = incl - c;  // exclusive prefix = segment start
}

__global__ void k_scatter() {
    int n = blockIdx.x * blockDim.x + threadIdx.x;
    int s = g_ix[n];
    int p = atomicAdd(&g_cursor[s], 1);
    g_perm[p] = n;
}

// ---------------- pass 1: fused logits + softmax + weighted segment mean ---
// One WARP per (b, segment). Lane l owns float4 slots {l, l+32, l+64, l+96}
// of the 512-dim row (every LDG.128 is a perfectly coalesced 512B warp
// access). Dot with Wg reduced via 5 shfls; no __syncthreads in the loop.
// Two rows per iteration so 8 LDG.128 are in flight per warp.
// Softmax max-shift is skipped: exp(l-m)/sum == exp(l)/sum exactly.
__global__ __launch_bounds__(256) void k_pass1(const float4* __restrict__ x4,
                                               const float4* __restrict__ Wg4,
                                               const float* __restrict__ bg) {
    int wid = threadIdx.x >> 5, lane = threadIdx.x & 31;
    int pair = blockIdx.x * 8 + wid;   // = b*S + s
    int b = pair >> 10;                // S = 1024
    int s = pair & (S - 1);

    float4 wgv[4];
#pragma unroll
    for (int j = 0; j < 4; j++) wgv[j] = Wg4[lane + 32 * j];
    float bg0 = bg[0];

    int start = g_offs[s], end = g_offs[s + 1];
    const float4* xb = x4 + (size_t)b * N * (D / 4);

    float4 acc[4];
#pragma unroll
    for (int j = 0; j < 4; j++) acc[j] = make_float4(0.f, 0.f, 0.f, 0.f);
    float denom = 0.f;

    for (int r = start; r < end; r += 2) {
        int n0 = g_perm[r];
        int n1 = (r + 1 < end) ? g_perm[r + 1] : n0;
        const float4* p0 = xb + (size_t)n0 * (D / 4);
        const float4* p1 = xb + (size_t)n1 * (D / 4);
        float4 xv0[4], xv1[4];
#pragma unroll
        for (int j = 0; j < 4; j++) xv0[j] = p0[lane + 32 * j];
#pragma unroll
        for (int j = 0; j < 4; j++) xv1[j] = p1[lane + 32 * j];

        float d0 = 0.f, d1 = 0.f;
#pragma unroll
        for (int j = 0; j < 4; j++) {
            d0 += xv0[j].x * wgv[j].x + xv0[j].y * wgv[j].y +
                  xv0[j].z * wgv[j].z + xv0[j].w * wgv[j].w;
            d1 += xv1[j].x * wgv[j].x + xv1[j].y * wgv[j].y +
                  xv1[j].z * wgv[j].z + xv1[j].w * wgv[j].w;
        }
#pragma unroll
        for (int off = 16; off; off >>= 1) {
            d0 += __shfl_xor_sync(~0u, d0, off);
            d1 += __shfl_xor_sync(~0u, d1, off);
        }
        float e0 = expf(d0 + bg0);
        float e1 = (r + 1 < end) ? expf(d1 + bg0) : 0.f;
        denom += e0 + e1;
#pragma unroll
        for (int j = 0; j < 4; j++) {
            acc[j].x += e0 * xv0[j].x + e1 * xv1[j].x;
            acc[j].y += e0 * xv0[j].y + e1 * xv1[j].y;
            acc[j].z += e0 * xv0[j].z + e1 * xv1[j].z;
            acc[j].w += e0 * xv0[j].w + e1 * xv1[j].w;
        }
    }
    float inv = (denom > 0.f) ? 1.f / denom : 0.f;
    float4* ob = (float4*)g_xbar + (size_t)pair * (D / 4);
#pragma unroll
    for (int j = 0; j < 4; j++) {
        float4 o = make_float4(acc[j].x * inv, acc[j].y * inv,
                               acc[j].z * inv, acc[j].w * inv);
        ob[lane + 32 * j] = o;
    }
}

// ---------------- fold weights: Wc = Wf @ Wh, bc = bf @ Wh + bh ----------------
__global__ void k_bc(const float* __restrict__ Wh, const float* __restrict__ bf,
                     const float* __restrict__ bh) {
    int d = blockIdx.x * blockDim.x + threadIdx.x;
    float acc = bh[d];
    for (int k = 0; k < D; k++) acc += bf[k] * Wh[(size_t)k * D + d];
    g_bc[d] = acc;
}

__global__ __launch_bounds__(256) void k_wc(const float* __restrict__ Wf,
                                            const float* __restrict__ Wh) {
    __shared__ float Af[32][33], Bf[32][33];
    int t = threadIdx.x;
    int row0 = blockIdx.y * 32, col0 = blockIdx.x * 32;
    int c = t & 31, g = t >> 5;
    float acc[4] = {0.f, 0.f, 0.f, 0.f};
    for (int k0 = 0; k0 < D; k0 += 32) {
#pragma unroll
        for (int i = 0; i < 4; i++) {
            int idx = t + i * 256;
            int r = idx >> 5, cc = idx & 31;
            Af[r][cc] = Wf[(size_t)(row0 + r) * D + k0 + cc];
            Bf[r][cc] = Wh[(size_t)(k0 + r) * D + col0 + cc];
        }
        __syncthreads();
#pragma unroll
        for (int k = 0; k < 32; k++) {
            float bv = Bf[k][c];
#pragma unroll
            for (int i = 0; i < 4; i++) acc[i] += Af[g * 4 + i][k] * bv;
        }
        __syncthreads();
    }
#pragma unroll
    for (int i = 0; i < 4; i++)
        g_Wc[(size_t)(row0 + g * 4 + i) * D + col0 + c] = acc[i];
}

// ---------------- z = xbar @ Wc + bc  (M=B*S=8192, N=K=512) ----------------
// 128x128x8 tiles, 256 threads, 8x8 per thread, accumulators as f32x2 pairs
// driven by packed fma.rn.f32x2 (FFMA2). launch_bounds(256,2) caps regs at
// 128 so 2 CTAs/SM fit and all 256 CTAs run in one wave.
__global__ __launch_bounds__(256, 2) void k_sgemm() {
    __shared__ float As[8][128];
    __shared__ float Bs[8][128];
    int bx = blockIdx.x, by = blockIdx.y;
    int t = threadIdx.x;
    int tx = t & 15, ty = t >> 4;
    const float* A = g_xbar + (size_t)by * 128 * D;
    const float* Bm = g_Wc + bx * 128;

    unsigned long long acc[8][4];
#pragma unroll
    for (int i = 0; i < 8; i++)
#pragma unroll
        for (int jp = 0; jp < 4; jp++) acc[i][jp] = 0ull;

    int arow = t >> 1, acol = (t & 1) * 4;   // A tile 128x8
    int brow = t >> 5, bcol = (t & 31) * 4;  // B tile 8x128

    for (int k0 = 0; k0 < D; k0 += 8) {
        float4 av = *(const float4*)(A + (size_t)arow * D + k0 + acol);
        float4 bv = *(const float4*)(Bm + (size_t)(k0 + brow) * D + bcol);
        __syncthreads();
        As[acol + 0][arow] = av.x;
        As[acol + 1][arow] = av.y;
        As[acol + 2][arow] = av.z;
        As[acol + 3][arow] = av.w;
        *(float4*)&Bs[brow][bcol] = bv;
        __syncthreads();
#pragma unroll
        for (int k = 0; k < 8; k++) {
            float4 a0 = *(const float4*)&As[k][ty * 4];
            float4 a1 = *(const float4*)&As[k][ty * 4 + 64];
            float4 b0 = *(const float4*)&Bs[k][tx * 4];
            float4 b1 = *(const float4*)&Bs[k][tx * 4 + 64];
            unsigned long long bp[4] = {pk2(b0.x, b0.y), pk2(b0.z, b0.w),
                                        pk2(b1.x, b1.y), pk2(b1.z, b1.w)};
            float ar[8] = {a0.x, a0.y, a0.z, a0.w, a1.x, a1.y, a1.z, a1.w};
#pragma unroll
            for (int i = 0; i < 8; i++) {
                unsigned long long ad = pk2(ar[i], ar[i]);
#pragma unroll
                for (int jp = 0; jp < 4; jp++) fma2(acc[i][jp], ad, bp[jp]);
            }
        }
    }

    float bb[8];
#pragma unroll
    for (int j = 0; j < 8; j++) {
        int nn = bx * 128 + ((j < 4) ? tx * 4 + j : 64 + tx * 4 + j - 4);
        bb[j] = g_bc[nn];
    }
#pragma unroll
    for (int i = 0; i < 8; i++) {
        int m = by * 128 + ((i < 4) ? ty * 4 + i : 64 + ty * 4 + i - 4);
        float* crow = g_z + (size_t)m * D + bx * 128;
        float2 c0 = upk2(acc[i][0]);
        float2 c1 = upk2(acc[i][1]);
        float2 c2 = upk2(acc[i][2]);
        float2 c3 = upk2(acc[i][3]);
        float4 o;
        o.x = c0.x + bb[0];
        o.y = c0.y + bb[1];
        o.z = c1.x + bb[2];
        o.w = c1.y + bb[3];
        *(float4*)(crow + tx * 4) = o;
        o.x = c2.x + bb[4];
        o.y = c2.y + bb[5];
        o.z = c3.x + bb[6];
        o.w = c3.y + bb[7];
        *(float4*)(crow + 64 + tx * 4) = o;
    }
}

// ---------------- gather/expand: out[b,n,:] = z[b, ix[n], :] ----------------
// Warp-per-row: lane l copies float4 slots {l, l+32, l+64, l+96}. z (16 MB)
// stays L2-resident because out writes use streaming (__stcs) eviction hint.
__global__ __launch_bounds__(256) void k_gather(float4* __restrict__ out4) {
    int wid = threadIdx.x >> 5, lane = threadIdx.x & 31;
    size_t row = (size_t)blockIdx.x * 8 + wid;  // b*N + n
    int n = (int)(row & (size_t)(N - 1));
    int b = (int)(row >> 16);  // N = 65536
    int s = g_ix[n];
    const float4* zp = (const float4*)g_z + ((size_t)(b * S + s)) * (D / 4);
    float4* op = out4 + row * (D / 4);
#pragma unroll
    for (int j = 0; j < 4; j++) {
        float4 v = zp[lane + 32 * j];
        __stcs(op + lane + 32 * j, v);
    }
}

// ---------------- launch ----------------
extern "C" void kernel_launch(void* const* d_in, const int* in_sizes, int n_in,
                              void* d_out, int out_size) {
    const float* x  = (const float*)d_in[0];
    const int*   ix = (const int*)d_in[1];
    const float* Wf = (const float*)d_in[2];
    const float* bf = (const float*)d_in[3];
    const float* Wg = (const float*)d_in[4];
    const float* bg = (const float*)d_in[5];
    const float* Wh = (const float*)d_in[6];
    const float* bh = (const float*)d_in[7];
    float* out = (float*)d_out;
    (void)in_sizes; (void)n_in; (void)out_size;

    k_fix_ix<<<N / 256, 256>>>(ix);
    k_count<<<N / 256, 256>>>();
    k_scan<<<1, S>>>();
    k_scatter<<<N / 256, 256>>>();

    k_pass1<<<(B * S) / 8, 256>>>((const float4*)x, (const float4*)Wg, bg);

    k_bc<<<D / 256, 256>>>(Wh, bf, bh);
    k_wc<<<dim3(D / 32, D / 32), 256>>>(Wf, Wh);

    k_sgemm<<<dim3(D / 128, (B * S) / 128), 256>>>();

    k_gather<<<(B * N) / 8, 256>>>((float4*)out);
}

// round 6
// speedup vs baseline: 1.4338x; 1.0253x over previous
#include <cuda_runtime.h>
#include <cstdint>

// Fixed problem shape (SoftAggBasic): x [B,N,D] f32, ix [N], S segments.
constexpr int B = 8;
constexpr int N = 65536;
constexpr int D = 512;
constexpr int S = 1024;
constexpr int PREP_CTAS = 4;
constexpr int ITEMS = N / (PREP_CTAS * 1024);  // 16

// ---------------- device scratch (no allocations allowed) ----------------
__device__ int   g_ix[N];
__device__ int   g_hist4[PREP_CTAS][S];
__device__ int   g_offs[S + 1];
__device__ int   g_cursor[S];
__device__ int   g_perm[N];
__device__ float g_xbar[(size_t)B * S * D];  // 16 MB
__device__ float g_Wc[(size_t)D * D];        // Wf @ Wh
__device__ float g_bc[D];                    // bf @ Wh + bh
__device__ float g_z[(size_t)B * S * D];     // 16 MB

// ---------------- packed f32x2 helpers (Blackwell FFMA2) ----------------
__device__ __forceinline__ unsigned long long pk2(float x, float y) {
    unsigned long long r;
    asm("mov.b64 %0, {%1,%2};" : "=l"(r) : "f"(x), "f"(y));
    return r;
}
__device__ __forceinline__ float2 upk2(unsigned long long v) {
    float2 r;
    asm("mov.b64 {%0,%1}, %2;" : "=f"(r.x), "=f"(r.y) : "l"(v));
    return r;
}
__device__ __forceinline__ void fma2(unsigned long long& d, unsigned long long a,
                                     unsigned long long b) {
    asm("fma.rn.f32x2 %0, %1, %2, %0;" : "+l"(d) : "l"(a), "l"(b));
}

// ---------------- prep 1: ix normalize + per-CTA histogram ----------------
// int64/int32 autodetect: for little-endian int64 values in [0,1024) every
// odd 32-bit word of the first 16 elements is 0; for int32 random data the
// probability of that is (1/1024)^16 ~ 0.
__global__ __launch_bounds__(1024) void k_prep1(const int* __restrict__ raw) {
    __shared__ int hist[S];
    int t = threadIdx.x, c = blockIdx.x;
    hist[t] = 0;
    int any = 0;
#pragma unroll
    for (int i = 0; i < 16; i++) any |= raw[2 * i + 1];
    __syncthreads();
    int base = c * (ITEMS * 1024);
#pragma unroll
    for (int i = 0; i < ITEMS; i++) {
        int n = base + i * 1024 + t;
        int v = (any == 0) ? raw[2 * n] : raw[n];
        g_ix[n] = v;
        atomicAdd(&hist[v], 1);
    }
    __syncthreads();
    g_hist4[c][t] = hist[t];
}

// single block, S=1024 threads, warp-shfl hierarchical scan
__global__ void k_scan() {
    __shared__ int ws[32];
    int t = threadIdx.x, lane = t & 31, w = t >> 5;
    int c = 0;
#pragma unroll
    for (int j = 0; j < PREP_CTAS; j++) c += g_hist4[j][t];
    int v = c;
#pragma unroll
    for (int off = 1; off < 32; off <<= 1) {
        int u = __shfl_up_sync(~0u, v, off);
        if (lane >= off) v += u;
    }
    if (lane == 31) ws[w] = v;
    __syncthreads();
    if (w == 0) {
        int s2 = ws[lane];
#pragma unroll
        for (int off = 1; off < 32; off <<= 1) {
            int u = __shfl_up_sync(~0u, s2, off);
            if (lane >= off) s2 += u;
        }
        ws[lane] = s2;
    }
    __syncthreads();
    int incl = v + (w ? ws[w - 1] : 0);
    g_offs[t + 1] = incl;
    if (t == 0) g_offs[0] = 0;
    g_cursor[t] = incl - c;  // exclusive prefix = segment start
}

// ---------------- prep 2: scatter with smem-aggregated reservation -------
// Local positions via smem atomics; ONE global atomicAdd per (CTA, bin)
// reserves a contiguous block inside the segment, so segments stay
// contiguous in g_perm while global atomic count drops 65536 -> 4096.
__global__ __launch_bounds__(1024) void k_prep2() {
    __shared__ int hist[S];
    __shared__ int basearr[S];
    int t = threadIdx.x, c = blockIdx.x;
    hist[t] = 0;
    __syncthreads();
    int base = c * (ITEMS * 1024);
    int lp[ITEMS], sv[ITEMS];
#pragma unroll
    for (int i = 0; i < ITEMS; i++) {
        int n = base + i * 1024 + t;
        int s = g_ix[n];
        sv[i] = s;
        lp[i] = atomicAdd(&hist[s], 1);
    }
    __syncthreads();
    basearr[t] = atomicAdd(&g_cursor[t], hist[t]);
    __syncthreads();
#pragma unroll
    for (int i = 0; i < ITEMS; i++)
        g_perm[basearr[sv[i]] + lp[i]] = base + i * 1024 + t;
}

// ---------------- pass 1: fused logits + softmax + weighted segment mean ---
// One WARP per (b, segment). Lane l owns float4 slots {l, l+32, l+64, l+96}
// (every LDG.128 is a perfectly coalesced 512B warp access). Dot with Wg
// reduced via 5 shfls; no __syncthreads in the loop. Two rows in flight.
// Softmax max-shift skipped: exp(l-m)/sum == exp(l)/sum exactly.
__global__ __launch_bounds__(256) void k_pass1(const float4* __restrict__ x4,
                                               const float4* __restrict__ Wg4,
                                               const float* __restrict__ bg) {
    int wid = threadIdx.x >> 5, lane = threadIdx.x & 31;
    int pair = blockIdx.x * 8 + wid;   // = b*S + s
    int b = pair >> 10;                // S = 1024
    int s = pair & (S - 1);

    float4 wgv[4];
#pragma unroll
    for (int j = 0; j < 4; j++) wgv[j] = Wg4[lane + 32 * j];
    float bg0 = bg[0];

    int start = g_offs[s], end = g_offs[s + 1];
    const float4* xb = x4 + (size_t)b * N * (D / 4);

    float4 acc[4];
#pragma unroll
    for (int j = 0; j < 4; j++) acc[j] = make_float4(0.f, 0.f, 0.f, 0.f);
    float denom = 0.f;

    for (int r = start; r < end; r += 2) {
        int n0 = g_perm[r];
        int n1 = (r + 1 < end) ? g_perm[r + 1] : n0;
        const float4* p0 = xb + (size_t)n0 * (D / 4);
        const float4* p1 = xb + (size_t)n1 * (D / 4);
        float4 xv0[4], xv1[4];
#pragma unroll
        for (int j = 0; j < 4; j++) xv0[j] = p0[lane + 32 * j];
#pragma unroll
        for (int j = 0; j < 4; j++) xv1[j] = p1[lane + 32 * j];

        float d0 = 0.f, d1 = 0.f;
#pragma unroll
        for (int j = 0; j < 4; j++) {
            d0 += xv0[j].x * wgv[j].x + xv0[j].y * wgv[j].y +
                  xv0[j].z * wgv[j].z + xv0[j].w * wgv[j].w;
            d1 += xv1[j].x * wgv[j].x + xv1[j].y * wgv[j].y +
                  xv1[j].z * wgv[j].z + xv1[j].w * wgv[j].w;
        }
#pragma unroll
        for (int off = 16; off; off >>= 1) {
            d0 += __shfl_xor_sync(~0u, d0, off);
            d1 += __shfl_xor_sync(~0u, d1, off);
        }
        float e0 = expf(d0 + bg0);
        float e1 = (r + 1 < end) ? expf(d1 + bg0) : 0.f;
        denom += e0 + e1;
#pragma unroll
        for (int j = 0; j < 4; j++) {
            acc[j].x += e0 * xv0[j].x + e1 * xv1[j].x;
            acc[j].y += e0 * xv0[j].y + e1 * xv1[j].y;
            acc[j].z += e0 * xv0[j].z + e1 * xv1[j].z;
            acc[j].w += e0 * xv0[j].w + e1 * xv1[j].w;
        }
    }
    float inv = (denom > 0.f) ? 1.f / denom : 0.f;
    float4* ob = (float4*)g_xbar + (size_t)pair * (D / 4);
#pragma unroll
    for (int j = 0; j < 4; j++)
        ob[lane + 32 * j] = make_float4(acc[j].x * inv, acc[j].y * inv,
                                        acc[j].z * inv, acc[j].w * inv);
}

// ---------------- fold weights: Wc = Wf @ Wh, bc = bf @ Wh + bh ----------------
__global__ void k_bc(const float* __restrict__ Wh, const float* __restrict__ bf,
                     const float* __restrict__ bh) {
    int d = blockIdx.x * blockDim.x + threadIdx.x;
    float acc = bh[d];
    for (int k = 0; k < D; k++) acc += bf[k] * Wh[(size_t)k * D + d];
    g_bc[d] = acc;
}

__global__ __launch_bounds__(256) void k_wc(const float* __restrict__ Wf,
                                            const float* __restrict__ Wh) {
    __shared__ float Af[32][33], Bf[32][33];
    int t = threadIdx.x;
    int row0 = blockIdx.y * 32, col0 = blockIdx.x * 32;
    int c = t & 31, g = t >> 5;
    float acc[4] = {0.f, 0.f, 0.f, 0.f};
    for (int k0 = 0; k0 < D; k0 += 32) {
#pragma unroll
        for (int i = 0; i < 4; i++) {
            int idx = t + i * 256;
            int r = idx >> 5, cc = idx & 31;
            Af[r][cc] = Wf[(size_t)(row0 + r) * D + k0 + cc];
            Bf[r][cc] = Wh[(size_t)(k0 + r) * D + col0 + cc];
        }
        __syncthreads();
#pragma unroll
        for (int k = 0; k < 32; k++) {
            float bv = Bf[k][c];
#pragma unroll
            for (int i = 0; i < 4; i++) acc[i] += Af[g * 4 + i][k] * bv;
        }
        __syncthreads();
    }
#pragma unroll
    for (int i = 0; i < 4; i++)
        g_Wc[(size_t)(row0 + g * 4 + i) * D + col0 + c] = acc[i];
}

// ---------------- z = xbar @ Wc + bc  (M=B*S=8192, N=K=512) ----------------
// 128x128x8 tiles, 256 threads, 8x8 per thread, f32x2 packed accumulators,
// DOUBLE-BUFFERED smem so global-load latency hides behind the 8-k compute.
// launch_bounds(256,2): 2 CTAs/SM, all 256 CTAs in ~1 wave.
__global__ __launch_bounds__(256, 2) void k_sgemm() {
    __shared__ float As[2][8][128];
    __shared__ float Bs[2][8][128];
    int bx = blockIdx.x, by = blockIdx.y;
    int t = threadIdx.x;
    int tx = t & 15, ty = t >> 4;
    const float* A = g_xbar + (size_t)by * 128 * D;
    const float* Bm = g_Wc + bx * 128;

    unsigned long long acc[8][4];
#pragma unroll
    for (int i = 0; i < 8; i++)
#pragma unroll
        for (int jp = 0; jp < 4; jp++) acc[i][jp] = 0ull;

    int arow = t >> 1, acol = (t & 1) * 4;   // A tile 128x8
    int brow = t >> 5, bcol = (t & 31) * 4;  // B tile 8x128

    // prologue: load k0 = 0 into buffer 0
    {
        float4 av = *(const float4*)(A + (size_t)arow * D + acol);
        float4 bv = *(const float4*)(Bm + (size_t)brow * D + bcol);
        As[0][acol + 0][arow] = av.x;
        As[0][acol + 1][arow] = av.y;
        As[0][acol + 2][arow] = av.z;
        As[0][acol + 3][arow] = av.w;
        *(float4*)&Bs[0][brow][bcol] = bv;
    }
    __syncthreads();

    int buf = 0;
    for (int k0 = 8; k0 <= D; k0 += 8) {
        float4 av2, bv2;
        if (k0 < D) {
            av2 = *(const float4*)(A + (size_t)arow * D + k0 + acol);
            bv2 = *(const float4*)(Bm + (size_t)(k0 + brow) * D + bcol);
        }
#pragma unroll
        for (int k = 0; k < 8; k++) {
            float4 a0 = *(const float4*)&As[buf][k][ty * 4];
            float4 a1 = *(const float4*)&As[buf][k][ty * 4 + 64];
            float4 b0 = *(const float4*)&Bs[buf][k][tx * 4];
            float4 b1 = *(const float4*)&Bs[buf][k][tx * 4 + 64];
            unsigned long long bp[4] = {pk2(b0.x, b0.y), pk2(b0.z, b0.w),
                                        pk2(b1.x, b1.y), pk2(b1.z, b1.w)};
            float ar[8] = {a0.x, a0.y, a0.z, a0.w, a1.x, a1.y, a1.z, a1.w};
#pragma unroll
            for (int i = 0; i < 8; i++) {
                unsigned long long ad = pk2(ar[i], ar[i]);
#pragma unroll
                for (int jp = 0; jp < 4; jp++) fma2(acc[i][jp], ad, bp[jp]);
            }
        }
        if (k0 < D) {
            int nb = buf ^ 1;
            As[nb][acol + 0][arow] = av2.x;
            As[nb][acol + 1][arow] = av2.y;
            As[nb][acol + 2][arow] = av2.z;
            As[nb][acol + 3][arow] = av2.w;
            *(float4*)&Bs[nb][brow][bcol] = bv2;
            __syncthreads();
            buf = nb;
        }
    }

    float bb[8];
#pragma unroll
    for (int j = 0; j < 8; j++) {
        int nn = bx * 128 + ((j < 4) ? tx * 4 + j : 64 + tx * 4 + j - 4);
        bb[j] = g_bc[nn];
    }
#pragma unroll
    for (int i = 0; i < 8; i++) {
        int m = by * 128 + ((i < 4) ? ty * 4 + i : 64 + ty * 4 + i - 4);
        float* crow = g_z + (size_t)m * D + bx * 128;
        float2 c0 = upk2(acc[i][0]);
        float2 c1 = upk2(acc[i][1]);
        float2 c2 = upk2(acc[i][2]);
        float2 c3 = upk2(acc[i][3]);
        float4 o;
        o.x = c0.x + bb[0];
        o.y = c0.y + bb[1];
        o.z = c1.x + bb[2];
        o.w = c1.y + bb[3];
        *(float4*)(crow + tx * 4) = o;
        o.x = c2.x + bb[4];
        o.y = c2.y + bb[5];
        o.z = c3.x + bb[6];
        o.w = c3.y + bb[7];
        *(float4*)(crow + 64 + tx * 4) = o;
    }
}

// ---------------- gather/expand: out[b,n,:] = z[b, ix[n], :] ----------------
// Warp-per-row; z (16 MB) stays L2-resident; out written with streaming hint.
__global__ __launch_bounds__(256) void k_gather(float4* __restrict__ out4) {
    int wid = threadIdx.x >> 5, lane = threadIdx.x & 31;
    size_t row = (size_t)blockIdx.x * 8 + wid;  // b*N + n
    int n = (int)(row & (size_t)(N - 1));
    int b = (int)(row >> 16);  // N = 65536
    int s = g_ix[n];
    const float4* zp = (const float4*)g_z + ((size_t)(b * S + s)) * (D / 4);
    float4* op = out4 + row * (D / 4);
#pragma unroll
    for (int j = 0; j < 4; j++) {
        float4 v = zp[lane + 32 * j];
        __stcs(op + lane + 32 * j, v);
    }
}

// ---------------- launch ----------------
extern "C" void kernel_launch(void* const* d_in, const int* in_sizes, int n_in,
                              void* d_out, int out_size) {
    const float* x  = (const float*)d_in[0];
    const int*   ix = (const int*)d_in[1];
    const float* Wf = (const float*)d_in[2];
    const float* bf = (const float*)d_in[3];
    const float* Wg = (const float*)d_in[4];
    const float* bg = (const float*)d_in[5];
    const float* Wh = (const float*)d_in[6];
    const float* bh = (const float*)d_in[7];
    float* out = (float*)d_out;
    (void)in_sizes; (void)n_in; (void)out_size;

    // slot 4 (= ncu capture slot) is k_pass1
    k_prep1<<<PREP_CTAS, 1024>>>(ix);
    k_scan<<<1, S>>>();
    k_prep2<<<PREP_CTAS, 1024>>>();
    k_pass1<<<(B * S) / 8, 256>>>((const float4*)x, (const float4*)Wg, bg);

    k_bc<<<D / 256, 256>>>(Wh, bf, bh);
    k_wc<<<dim3(D / 32, D / 32), 256>>>(Wf, Wh);

    k_sgemm<<<dim3(D / 128, (B * S) / 128), 256>>>();

    k_gather<<<(B * N) / 8, 256>>>((float4*)out);
}